// round 6
// baseline (speedup 1.0000x reference)
#include <cuda_runtime.h>
#include <cuda_fp16.h>

#define D 128
#define NEG 0.01f
#define NMAX 100000
#define EMAX 2000000
#define NBMAX 128   // scan blocks: ceil(NMAX/1024) = 98
#define LDS_PAD 8
#define LDA (D + LDS_PAD)

// Scratch (allocation-free rule: __device__ globals)
__device__ __half2 g_h[NMAX * 64];     // H' = (X' @ W) * dinv_row, fp16
__device__ __half2 g_x2[NMAX * 64];    // layer-2 input, fp16
__device__ __half  g_w1h[D * D];
__device__ __half  g_w2h[D * D];
__device__ float g_dinv[NMAX];
__device__ int   g_cnt[NMAX];
__device__ int   g_rptr[NMAX + 1];
__device__ int   g_cursor[NMAX];
__device__ int   g_partial[NMAX];
__device__ int   g_bsum[NBMAX];
__device__ int   g_col[EMAX];

// ---------------------------------------------------------------------------
// Setup: zero degree counters + convert both weight matrices to fp16
// ---------------------------------------------------------------------------
__global__ void k_setup(const float* __restrict__ W1, const float* __restrict__ W2, int n) {
    int i = blockIdx.x * blockDim.x + threadIdx.x;
    if (i < n) g_cnt[i] = 0;
    if (i < D * D) {
        g_w1h[i] = __float2half(W1[i]);
        g_w2h[i] = __float2half(W2[i]);
    }
}

__global__ void k_count(const int* __restrict__ dst, int e) {
    int i = blockIdx.x * blockDim.x + threadIdx.x;
    if (i < e) atomicAdd(&g_cnt[dst[i]], 1);
}

// dinv only (unblocks GEMM1 before the CSR scan)
__global__ void k_dinv(int n) {
    int i = blockIdx.x * blockDim.x + threadIdx.x;
    if (i < n) g_dinv[i] = rsqrtf((float)g_cnt[i] + 1.0f);
}

// block-wise inclusive scan of g_cnt
__global__ void __launch_bounds__(1024) k_scan_block(int n) {
    __shared__ int sh[1024];
    int i = blockIdx.x * 1024 + threadIdx.x;
    int v = (i < n) ? g_cnt[i] : 0;
    sh[threadIdx.x] = v;
#pragma unroll
    for (int off = 1; off < 1024; off <<= 1) {
        __syncthreads();
        int t = (threadIdx.x >= off) ? sh[threadIdx.x - off] : 0;
        __syncthreads();
        sh[threadIdx.x] += t;
    }
    if (i < n) g_partial[i] = sh[threadIdx.x];
    if (threadIdx.x == 1023) g_bsum[blockIdx.x] = sh[1023];
}

// finalize rptr/cursor; block-sum scan redundantly per block (warp 0)
__global__ void __launch_bounds__(256) k_finalize(int n, int nb) {
    __shared__ int boff_s[NBMAX];
    if (threadIdx.x < 32) {
        int t = threadIdx.x;
        int b = t * 4;
        int s0 = (b + 0 < nb) ? g_bsum[b + 0] : 0;
        int s1 = (b + 1 < nb) ? g_bsum[b + 1] : 0;
        int s2 = (b + 2 < nb) ? g_bsum[b + 2] : 0;
        int s3 = (b + 3 < nb) ? g_bsum[b + 3] : 0;
        int tot = s0 + s1 + s2 + s3;
        int x = tot;
#pragma unroll
        for (int o = 1; o < 32; o <<= 1) {
            int y = __shfl_up_sync(0xffffffffu, x, o);
            if (t >= o) x += y;
        }
        int excl = x - tot;
        if (b + 0 < NBMAX) boff_s[b + 0] = excl;
        if (b + 1 < NBMAX) boff_s[b + 1] = excl + s0;
        if (b + 2 < NBMAX) boff_s[b + 2] = excl + s0 + s1;
        if (b + 3 < NBMAX) boff_s[b + 3] = excl + s0 + s1 + s2;
    }
    __syncthreads();
    int i = blockIdx.x * blockDim.x + threadIdx.x;
    if (i >= n) return;
    int incl = g_partial[i] + boff_s[i >> 10];
    g_rptr[i + 1] = incl;
    g_cursor[i] = incl - g_cnt[i];
    if (i == 0) g_rptr[0] = 0;
}

__global__ void k_fill(const int* __restrict__ src, const int* __restrict__ dst, int e) {
    int i = blockIdx.x * blockDim.x + threadIdx.x;
    if (i < e) {
        int d = dst[i];
        int pos = atomicAdd(&g_cursor[d], 1);
        g_col[pos] = src[i];
    }
}

// ---------------------------------------------------------------------------
// Tensor-core GEMM: H'[n,128](fp16) = (X[n,128] @ W[128,128]) * dinv[row]
// 8 warps as 4(m)x2(n); warp tile 32 rows x 64 cols -> fewer LDSM per MMA.
// ---------------------------------------------------------------------------
template <typename TA>
__global__ void __launch_bounds__(256)
k_gemm_tc(const TA* __restrict__ X, const __half* __restrict__ Wh,
          __half2* __restrict__ H, int n)
{
    extern __shared__ __half sm[];
    __half* As = sm;                 // [128][LDA]
    __half* Ws = sm + 128 * LDA;     // [128][LDA]

    const int t    = threadIdx.x;
    const int wid  = t >> 5;
    const int lane = t & 31;
    const int row0 = blockIdx.x * 128;

    {   // W tile
        int wr = t >> 1;
        int wc = (t & 1) << 6;
#pragma unroll
        for (int j = 0; j < 8; j++) {
            uint4 u = *(const uint4*)&Wh[wr * D + wc + j * 8];
            *(uint4*)&Ws[wr * LDA + wc + j * 8] = u;
        }
    }
    {   // A tile (convert fp32 -> fp16 if needed)
        int ar = t >> 1;
        int ac = (t & 1) << 6;
        int r = row0 + ar;
        if (r < n) {
            if constexpr (sizeof(TA) == 4) {
                const float* Xr = (const float*)X + (size_t)r * D + ac;
#pragma unroll
                for (int j = 0; j < 8; j++) {
                    float4 f0 = *(const float4*)&Xr[j * 8];
                    float4 f1 = *(const float4*)&Xr[j * 8 + 4];
                    __half2 h0 = __floats2half2_rn(f0.x, f0.y);
                    __half2 h1 = __floats2half2_rn(f0.z, f0.w);
                    __half2 h2 = __floats2half2_rn(f1.x, f1.y);
                    __half2 h3 = __floats2half2_rn(f1.z, f1.w);
                    uint4 u;
                    u.x = *(unsigned*)&h0; u.y = *(unsigned*)&h1;
                    u.z = *(unsigned*)&h2; u.w = *(unsigned*)&h3;
                    *(uint4*)&As[ar * LDA + ac + j * 8] = u;
                }
            } else {
                const __half* Xr = (const __half*)X + (size_t)r * D + ac;
#pragma unroll
                for (int j = 0; j < 8; j++)
                    *(uint4*)&As[ar * LDA + ac + j * 8] = *(const uint4*)&Xr[j * 8];
            }
        } else {
            uint4 z = make_uint4(0, 0, 0, 0);
#pragma unroll
            for (int j = 0; j < 8; j++)
                *(uint4*)&As[ar * LDA + ac + j * 8] = z;
        }
    }
    __syncthreads();

    // warp tile: rows [m0, m0+32), cols [n0, n0+64)
    const int m0 = (wid >> 1) << 5;
    const int n0 = (wid & 1) << 6;

    float acc[2][8][4];   // [m-frag][n8][4]
#pragma unroll
    for (int mi = 0; mi < 2; mi++)
#pragma unroll
        for (int j = 0; j < 8; j++)
#pragma unroll
            for (int q = 0; q < 4; q++) acc[mi][j][q] = 0.0f;

    const __half* a_base = As + (m0 + (lane & 15)) * LDA + ((lane >> 4) << 3);
    const __half* b_base = Ws + (lane & 15) * LDA + n0 + ((lane >> 4) << 3);

#pragma unroll
    for (int ks = 0; ks < 8; ks++) {
        unsigned a[2][4];
#pragma unroll
        for (int mi = 0; mi < 2; mi++) {
            unsigned sa = (unsigned)__cvta_generic_to_shared(
                a_base + (mi << 4) * LDA + ks * 16);
            asm volatile("ldmatrix.sync.aligned.m8n8.x4.shared.b16 {%0,%1,%2,%3}, [%4];"
                         : "=r"(a[mi][0]), "=r"(a[mi][1]), "=r"(a[mi][2]), "=r"(a[mi][3])
                         : "r"(sa));
        }
#pragma unroll
        for (int ni = 0; ni < 4; ni++) {
            unsigned b0, b1, b2, b3;
            unsigned sb = (unsigned)__cvta_generic_to_shared(
                b_base + (ks * 16) * LDA + ni * 16);
            asm volatile("ldmatrix.sync.aligned.m8n8.x4.trans.shared.b16 {%0,%1,%2,%3}, [%4];"
                         : "=r"(b0), "=r"(b1), "=r"(b2), "=r"(b3) : "r"(sb));
#pragma unroll
            for (int mi = 0; mi < 2; mi++) {
                float* c = acc[mi][2 * ni];
                asm volatile("mma.sync.aligned.m16n8k16.row.col.f32.f16.f16.f32 "
                             "{%0,%1,%2,%3}, {%4,%5,%6,%7}, {%8,%9}, {%0,%1,%2,%3};"
                             : "+f"(c[0]), "+f"(c[1]), "+f"(c[2]), "+f"(c[3])
                             : "r"(a[mi][0]), "r"(a[mi][1]), "r"(a[mi][2]), "r"(a[mi][3]),
                               "r"(b0), "r"(b1));
                float* c2 = acc[mi][2 * ni + 1];
                asm volatile("mma.sync.aligned.m16n8k16.row.col.f32.f16.f16.f32 "
                             "{%0,%1,%2,%3}, {%4,%5,%6,%7}, {%8,%9}, {%0,%1,%2,%3};"
                             : "+f"(c2[0]), "+f"(c2[1]), "+f"(c2[2]), "+f"(c2[3])
                             : "r"(a[mi][0]), "r"(a[mi][1]), "r"(a[mi][2]), "r"(a[mi][3]),
                               "r"(b2), "r"(b3));
            }
        }
    }

    // epilogue: prescale by dinv[row], store fp16
    __half* Hp = (__half*)H;
    const int cb = (lane & 3) << 1;
#pragma unroll
    for (int mi = 0; mi < 2; mi++) {
        const int r0 = row0 + m0 + (mi << 4) + (lane >> 2);
        const float d0 = (r0 < n)     ? g_dinv[r0]     : 0.0f;
        const float d1 = (r0 + 8 < n) ? g_dinv[r0 + 8] : 0.0f;
#pragma unroll
        for (int ni = 0; ni < 4; ni++) {
#pragma unroll
            for (int half8 = 0; half8 < 2; half8++) {
                float* c = acc[mi][2 * ni + half8];
                int col = n0 + ni * 16 + half8 * 8 + cb;
                if (r0 < n) {
                    __half2 v = __floats2half2_rn(c[0] * d0, c[1] * d0);
                    *(unsigned*)&Hp[(size_t)r0 * D + col] = *(unsigned*)&v;
                }
                if (r0 + 8 < n) {
                    __half2 v = __floats2half2_rn(c[2] * d1, c[3] * d1);
                    *(unsigned*)&Hp[(size_t)(r0 + 8) * D + col] = *(unsigned*)&v;
                }
            }
        }
    }
}

// ---------------------------------------------------------------------------
// Aggregation (CSR gather, prescaled fp16 H'):
//   out[d] = leakyrelu( dinv_d * (H'[d] + sum_{s in N(d)} H'[s]) + bias )
// ---------------------------------------------------------------------------
template <int OUTHALF>
__global__ void __launch_bounds__(256)
k_agg(const __half2* __restrict__ H, const float* __restrict__ bias,
      void* __restrict__ outp, int n)
{
    int node = (blockIdx.x * blockDim.x + threadIdx.x) >> 5;
    int lane = threadIdx.x & 31;
    if (node >= n) return;

    uint2 u = *(const uint2*)(H + (size_t)node * 64 + (lane << 1));
    float2 f0 = __half22float2(*(__half2*)&u.x);
    float2 f1 = __half22float2(*(__half2*)&u.y);
    float4 acc = make_float4(f0.x, f0.y, f1.x, f1.y);   // self term

    int beg = g_rptr[node], end = g_rptr[node + 1];
    for (int j = beg; j < end; j += 32) {
        int idx = j + lane;
        int s = (idx < end) ? g_col[idx] : 0;
        int cnt = min(32, end - j);
        for (int t = 0; t < cnt; t++) {
            int ss = __shfl_sync(0xffffffffu, s, t);
            uint2 hu = *(const uint2*)(H + (size_t)ss * 64 + (lane << 1));
            float2 h0 = __half22float2(*(__half2*)&hu.x);
            float2 h1 = __half22float2(*(__half2*)&hu.y);
            acc.x += h0.x; acc.y += h0.y;
            acc.z += h1.x; acc.w += h1.y;
        }
    }

    float dd = g_dinv[node];
    float4 b = *(const float4*)&bias[lane << 2];
    acc.x = fmaf(acc.x, dd, b.x);
    acc.y = fmaf(acc.y, dd, b.y);
    acc.z = fmaf(acc.z, dd, b.z);
    acc.w = fmaf(acc.w, dd, b.w);
    acc.x = fmaxf(acc.x, NEG * acc.x);
    acc.y = fmaxf(acc.y, NEG * acc.y);
    acc.z = fmaxf(acc.z, NEG * acc.z);
    acc.w = fmaxf(acc.w, NEG * acc.w);

    if (OUTHALF) {
        __half2 h0 = __floats2half2_rn(acc.x, acc.y);
        __half2 h1 = __floats2half2_rn(acc.z, acc.w);
        uint2 o; o.x = *(unsigned*)&h0; o.y = *(unsigned*)&h1;
        *(uint2*)((__half2*)outp + (size_t)node * 64 + (lane << 1)) = o;
    } else {
        *(float4*)((float*)outp + (size_t)node * D + (lane << 2)) = acc;
    }
}

// ---------------------------------------------------------------------------
extern "C" void kernel_launch(void* const* d_in, const int* in_sizes, int n_in,
                              void* d_out, int out_size)
{
    const float* x  = (const float*)d_in[0];
    const float* W1 = (const float*)d_in[1];
    const float* b1 = (const float*)d_in[2];
    const float* W2 = (const float*)d_in[3];
    const float* b2 = (const float*)d_in[4];
    const int*   ei = (const int*)d_in[5];

    const int n = in_sizes[0] / D;
    const int e = in_sizes[5] / 2;
    const int* src = ei;
    const int* dst = ei + e;

    __half2 *h, *x2;
    __half *w1h, *w2h;
    cudaGetSymbolAddress((void**)&h,   g_h);
    cudaGetSymbolAddress((void**)&x2,  g_x2);
    cudaGetSymbolAddress((void**)&w1h, g_w1h);
    cudaGetSymbolAddress((void**)&w2h, g_w2h);

    const int smem = 2 * 128 * LDA * (int)sizeof(__half);
    static cudaStream_t s2 = nullptr;
    static cudaEvent_t ev1 = nullptr, ev2 = nullptr;
    if (!s2) {  // one-time host-resource setup
        cudaFuncSetAttribute(k_gemm_tc<float>,
                             cudaFuncAttributeMaxDynamicSharedMemorySize, smem);
        cudaFuncSetAttribute(k_gemm_tc<__half>,
                             cudaFuncAttributeMaxDynamicSharedMemorySize, smem);
        cudaStreamCreateWithFlags(&s2, cudaStreamNonBlocking);
        cudaEventCreateWithFlags(&ev1, cudaEventDisableTiming);
        cudaEventCreateWithFlags(&ev2, cudaEventDisableTiming);
    }

    const int gemm_blocks = (n + 127) / 128;
    const int agg_blocks  = (int)(((long long)n * 32 + 255) / 256);
    const int nb = (n + 1023) / 1024;

    // setup + degree count + dinv (dinv unblocks GEMM1)
    k_setup<<<(n + 255) / 256, 256>>>(W1, W2, n);
    k_count<<<(e + 255) / 256, 256>>>(dst, e);
    k_dinv<<<(n + 255) / 256, 256>>>(n);

    // fork: GEMM1 on side stream; CSR scan/finalize/fill on main stream
    cudaEventRecord(ev1, 0);
    cudaStreamWaitEvent(s2, ev1, 0);
    k_gemm_tc<float><<<gemm_blocks, 256, smem, s2>>>(x, w1h, h, n);
    cudaEventRecord(ev2, s2);

    k_scan_block<<<nb, 1024>>>(n);
    k_finalize<<<(n + 255) / 256, 256>>>(n, nb);
    k_fill<<<(e + 255) / 256, 256>>>(src, dst, e);
    cudaStreamWaitEvent(0, ev2, 0);

    // layer 1 aggregation -> fp16 x2
    k_agg<1><<<agg_blocks, 256>>>(h, b1, x2, n);

    // layer 2
    k_gemm_tc<__half><<<gemm_blocks, 256, smem>>>((const __half*)x2, w2h, h, n);
    k_agg<0><<<agg_blocks, 256>>>(h, b2, d_out, n);
}

// round 7
// speedup vs baseline: 1.3275x; 1.3275x over previous
#include <cuda_runtime.h>
#include <cuda_fp16.h>

#define D 128
#define NEG 0.01f
#define NMAX 100000
#define EMAX 2000000
#define NBMAX 128   // scan blocks: ceil(NMAX/1024) = 98
#define LDS_PAD 8
#define LDA (D + LDS_PAD)

// Scratch (allocation-free rule: __device__ globals)
__device__ __half2 g_h[NMAX * 64];     // H' = (X' @ W) * dinv_row, fp16
__device__ __half2 g_x2[NMAX * 64];    // layer-2 input, fp16
__device__ __half  g_w1h[D * D];
__device__ __half  g_w2h[D * D];
__device__ float g_dinv[NMAX];
__device__ int   g_cnt[NMAX];
__device__ int   g_rptr[NMAX + 1];
__device__ int   g_cursor[NMAX];
__device__ int   g_partial[NMAX];
__device__ int   g_bsum[NBMAX];
__device__ int   g_col[EMAX];

// ---------------------------------------------------------------------------
// Setup: zero degree counters + convert both weight matrices to fp16
// ---------------------------------------------------------------------------
__global__ void k_setup(const float* __restrict__ W1, const float* __restrict__ W2, int n) {
    int i = blockIdx.x * blockDim.x + threadIdx.x;
    if (i < n) g_cnt[i] = 0;
    if (i < D * D) {
        g_w1h[i] = __float2half(W1[i]);
        g_w2h[i] = __float2half(W2[i]);
    }
}

__global__ void k_count(const int* __restrict__ dst, int e) {
    int i = blockIdx.x * blockDim.x + threadIdx.x;
    if (i < e) atomicAdd(&g_cnt[dst[i]], 1);
}

// dinv only (unblocks GEMM1 before the CSR scan)
__global__ void k_dinv(int n) {
    int i = blockIdx.x * blockDim.x + threadIdx.x;
    if (i < n) g_dinv[i] = rsqrtf((float)g_cnt[i] + 1.0f);
}

// block-wise inclusive scan of g_cnt
__global__ void __launch_bounds__(1024) k_scan_block(int n) {
    __shared__ int sh[1024];
    int i = blockIdx.x * 1024 + threadIdx.x;
    int v = (i < n) ? g_cnt[i] : 0;
    sh[threadIdx.x] = v;
#pragma unroll
    for (int off = 1; off < 1024; off <<= 1) {
        __syncthreads();
        int t = (threadIdx.x >= off) ? sh[threadIdx.x - off] : 0;
        __syncthreads();
        sh[threadIdx.x] += t;
    }
    if (i < n) g_partial[i] = sh[threadIdx.x];
    if (threadIdx.x == 1023) g_bsum[blockIdx.x] = sh[1023];
}

// finalize rptr/cursor; block-sum scan redundantly per block (warp 0)
__global__ void __launch_bounds__(256) k_finalize(int n, int nb) {
    __shared__ int boff_s[NBMAX];
    if (threadIdx.x < 32) {
        int t = threadIdx.x;
        int b = t * 4;
        int s0 = (b + 0 < nb) ? g_bsum[b + 0] : 0;
        int s1 = (b + 1 < nb) ? g_bsum[b + 1] : 0;
        int s2 = (b + 2 < nb) ? g_bsum[b + 2] : 0;
        int s3 = (b + 3 < nb) ? g_bsum[b + 3] : 0;
        int tot = s0 + s1 + s2 + s3;
        int x = tot;
#pragma unroll
        for (int o = 1; o < 32; o <<= 1) {
            int y = __shfl_up_sync(0xffffffffu, x, o);
            if (t >= o) x += y;
        }
        int excl = x - tot;
        if (b + 0 < NBMAX) boff_s[b + 0] = excl;
        if (b + 1 < NBMAX) boff_s[b + 1] = excl + s0;
        if (b + 2 < NBMAX) boff_s[b + 2] = excl + s0 + s1;
        if (b + 3 < NBMAX) boff_s[b + 3] = excl + s0 + s1 + s2;
    }
    __syncthreads();
    int i = blockIdx.x * blockDim.x + threadIdx.x;
    if (i >= n) return;
    int incl = g_partial[i] + boff_s[i >> 10];
    g_rptr[i + 1] = incl;
    g_cursor[i] = incl - g_cnt[i];
    if (i == 0) g_rptr[0] = 0;
}

__global__ void k_fill(const int* __restrict__ src, const int* __restrict__ dst, int e) {
    int i = blockIdx.x * blockDim.x + threadIdx.x;
    if (i < e) {
        int d = dst[i];
        int pos = atomicAdd(&g_cursor[d], 1);
        g_col[pos] = src[i];
    }
}

// ---------------------------------------------------------------------------
// Tensor-core GEMM: H'[n,128](fp16) = (X[n,128] @ W[128,128]) * dinv[row]
// Round-5 shape: 8 warps, warp w owns rows [16w,16w+16) x all 128 cols.
// Non-volatile asm so ptxas can software-pipeline LDSM across MMA.
// ---------------------------------------------------------------------------
template <typename TA>
__global__ void __launch_bounds__(256)
k_gemm_tc(const TA* __restrict__ X, const __half* __restrict__ Wh,
          __half2* __restrict__ H, int n)
{
    extern __shared__ __half sm[];
    __half* As = sm;                 // [128][LDA]
    __half* Ws = sm + 128 * LDA;     // [128][LDA]

    const int t    = threadIdx.x;
    const int wid  = t >> 5;
    const int lane = t & 31;
    const int row0 = blockIdx.x * 128;

    {   // W tile
        int wr = t >> 1;
        int wc = (t & 1) << 6;
#pragma unroll
        for (int j = 0; j < 8; j++) {
            uint4 u = *(const uint4*)&Wh[wr * D + wc + j * 8];
            *(uint4*)&Ws[wr * LDA + wc + j * 8] = u;
        }
    }
    {   // A tile (convert fp32 -> fp16 if needed)
        int ar = t >> 1;
        int ac = (t & 1) << 6;
        int r = row0 + ar;
        if (r < n) {
            if constexpr (sizeof(TA) == 4) {
                const float* Xr = (const float*)X + (size_t)r * D + ac;
#pragma unroll
                for (int j = 0; j < 8; j++) {
                    float4 f0 = *(const float4*)&Xr[j * 8];
                    float4 f1 = *(const float4*)&Xr[j * 8 + 4];
                    __half2 h0 = __floats2half2_rn(f0.x, f0.y);
                    __half2 h1 = __floats2half2_rn(f0.z, f0.w);
                    __half2 h2 = __floats2half2_rn(f1.x, f1.y);
                    __half2 h3 = __floats2half2_rn(f1.z, f1.w);
                    uint4 u;
                    u.x = *(unsigned*)&h0; u.y = *(unsigned*)&h1;
                    u.z = *(unsigned*)&h2; u.w = *(unsigned*)&h3;
                    *(uint4*)&As[ar * LDA + ac + j * 8] = u;
                }
            } else {
                const __half* Xr = (const __half*)X + (size_t)r * D + ac;
#pragma unroll
                for (int j = 0; j < 8; j++)
                    *(uint4*)&As[ar * LDA + ac + j * 8] = *(const uint4*)&Xr[j * 8];
            }
        } else {
            uint4 z = make_uint4(0, 0, 0, 0);
#pragma unroll
            for (int j = 0; j < 8; j++)
                *(uint4*)&As[ar * LDA + ac + j * 8] = z;
        }
    }
    __syncthreads();

    float acc[16][4];
#pragma unroll
    for (int i = 0; i < 16; i++)
#pragma unroll
        for (int j = 0; j < 4; j++) acc[i][j] = 0.0f;

    const int m0 = wid << 4;
    const __half* a_base = As + (m0 + (lane & 15)) * LDA + ((lane >> 4) << 3);
    const __half* b_base = Ws + (lane & 15) * LDA + ((lane >> 4) << 3);

#pragma unroll
    for (int ks = 0; ks < 8; ks++) {
        unsigned a0, a1, a2, a3;
        {
            unsigned sa = (unsigned)__cvta_generic_to_shared(a_base + ks * 16);
            asm("ldmatrix.sync.aligned.m8n8.x4.shared.b16 {%0,%1,%2,%3}, [%4];"
                : "=r"(a0), "=r"(a1), "=r"(a2), "=r"(a3) : "r"(sa));
        }
#pragma unroll
        for (int nc = 0; nc < 8; nc++) {
            unsigned b0, b1, b2, b3;
            unsigned sb = (unsigned)__cvta_generic_to_shared(
                b_base + (ks * 16) * LDA + nc * 16);
            asm("ldmatrix.sync.aligned.m8n8.x4.trans.shared.b16 {%0,%1,%2,%3}, [%4];"
                : "=r"(b0), "=r"(b1), "=r"(b2), "=r"(b3) : "r"(sb));
            float* c = acc[2 * nc];
            asm("mma.sync.aligned.m16n8k16.row.col.f32.f16.f16.f32 "
                "{%0,%1,%2,%3}, {%4,%5,%6,%7}, {%8,%9}, {%0,%1,%2,%3};"
                : "+f"(c[0]), "+f"(c[1]), "+f"(c[2]), "+f"(c[3])
                : "r"(a0), "r"(a1), "r"(a2), "r"(a3), "r"(b0), "r"(b1));
            float* c2 = acc[2 * nc + 1];
            asm("mma.sync.aligned.m16n8k16.row.col.f32.f16.f16.f32 "
                "{%0,%1,%2,%3}, {%4,%5,%6,%7}, {%8,%9}, {%0,%1,%2,%3};"
                : "+f"(c2[0]), "+f"(c2[1]), "+f"(c2[2]), "+f"(c2[3])
                : "r"(a0), "r"(a1), "r"(a2), "r"(a3), "r"(b2), "r"(b3));
        }
    }

    // epilogue: prescale by dinv[row], store fp16
    __half* Hp = (__half*)H;
    const int r0 = row0 + m0 + (lane >> 2);
    const int cb = (lane & 3) << 1;
    const float d0 = (r0 < n)     ? g_dinv[r0]     : 0.0f;
    const float d1 = (r0 + 8 < n) ? g_dinv[r0 + 8] : 0.0f;
#pragma unroll
    for (int nc = 0; nc < 8; nc++) {
#pragma unroll
        for (int half8 = 0; half8 < 2; half8++) {
            float* c = acc[2 * nc + half8];
            int col = nc * 16 + half8 * 8 + cb;
            if (r0 < n) {
                __half2 v = __floats2half2_rn(c[0] * d0, c[1] * d0);
                *(unsigned*)&Hp[(size_t)r0 * D + col] = *(unsigned*)&v;
            }
            if (r0 + 8 < n) {
                __half2 v = __floats2half2_rn(c[2] * d1, c[3] * d1);
                *(unsigned*)&Hp[(size_t)(r0 + 8) * D + col] = *(unsigned*)&v;
            }
        }
    }
}

// ---------------------------------------------------------------------------
// Aggregation (CSR gather, prescaled fp16 H'):
//   out[d] = leakyrelu( dinv_d * (H'[d] + sum_{s in N(d)} H'[s]) + bias )
// ---------------------------------------------------------------------------
template <int OUTHALF>
__global__ void __launch_bounds__(256)
k_agg(const __half2* __restrict__ H, const float* __restrict__ bias,
      void* __restrict__ outp, int n)
{
    int node = (blockIdx.x * blockDim.x + threadIdx.x) >> 5;
    int lane = threadIdx.x & 31;
    if (node >= n) return;

    uint2 u = *(const uint2*)(H + (size_t)node * 64 + (lane << 1));
    float2 f0 = __half22float2(*(__half2*)&u.x);
    float2 f1 = __half22float2(*(__half2*)&u.y);
    float4 acc = make_float4(f0.x, f0.y, f1.x, f1.y);   // self term

    int beg = g_rptr[node], end = g_rptr[node + 1];
    for (int j = beg; j < end; j += 32) {
        int idx = j + lane;
        int s = (idx < end) ? g_col[idx] : 0;
        int cnt = min(32, end - j);
        for (int t = 0; t < cnt; t++) {
            int ss = __shfl_sync(0xffffffffu, s, t);
            uint2 hu = *(const uint2*)(H + (size_t)ss * 64 + (lane << 1));
            float2 h0 = __half22float2(*(__half2*)&hu.x);
            float2 h1 = __half22float2(*(__half2*)&hu.y);
            acc.x += h0.x; acc.y += h0.y;
            acc.z += h1.x; acc.w += h1.y;
        }
    }

    float dd = g_dinv[node];
    float4 b = *(const float4*)&bias[lane << 2];
    acc.x = fmaf(acc.x, dd, b.x);
    acc.y = fmaf(acc.y, dd, b.y);
    acc.z = fmaf(acc.z, dd, b.z);
    acc.w = fmaf(acc.w, dd, b.w);
    acc.x = fmaxf(acc.x, NEG * acc.x);
    acc.y = fmaxf(acc.y, NEG * acc.y);
    acc.z = fmaxf(acc.z, NEG * acc.z);
    acc.w = fmaxf(acc.w, NEG * acc.w);

    if (OUTHALF) {
        __half2 h0 = __floats2half2_rn(acc.x, acc.y);
        __half2 h1 = __floats2half2_rn(acc.z, acc.w);
        uint2 o; o.x = *(unsigned*)&h0; o.y = *(unsigned*)&h1;
        *(uint2*)((__half2*)outp + (size_t)node * 64 + (lane << 1)) = o;
    } else {
        *(float4*)((float*)outp + (size_t)node * D + (lane << 2)) = acc;
    }
}

// ---------------------------------------------------------------------------
extern "C" void kernel_launch(void* const* d_in, const int* in_sizes, int n_in,
                              void* d_out, int out_size)
{
    const float* x  = (const float*)d_in[0];
    const float* W1 = (const float*)d_in[1];
    const float* b1 = (const float*)d_in[2];
    const float* W2 = (const float*)d_in[3];
    const float* b2 = (const float*)d_in[4];
    const int*   ei = (const int*)d_in[5];

    const int n = in_sizes[0] / D;
    const int e = in_sizes[5] / 2;
    const int* src = ei;
    const int* dst = ei + e;

    __half2 *h, *x2;
    __half *w1h, *w2h;
    cudaGetSymbolAddress((void**)&h,   g_h);
    cudaGetSymbolAddress((void**)&x2,  g_x2);
    cudaGetSymbolAddress((void**)&w1h, g_w1h);
    cudaGetSymbolAddress((void**)&w2h, g_w2h);

    const int smem = 2 * 128 * LDA * (int)sizeof(__half);
    static cudaStream_t s2 = nullptr;
    static cudaEvent_t ev1 = nullptr, ev2 = nullptr;
    if (!s2) {  // one-time host-resource setup
        cudaFuncSetAttribute(k_gemm_tc<float>,
                             cudaFuncAttributeMaxDynamicSharedMemorySize, smem);
        cudaFuncSetAttribute(k_gemm_tc<__half>,
                             cudaFuncAttributeMaxDynamicSharedMemorySize, smem);
        cudaStreamCreateWithFlags(&s2, cudaStreamNonBlocking);
        cudaEventCreateWithFlags(&ev1, cudaEventDisableTiming);
        cudaEventCreateWithFlags(&ev2, cudaEventDisableTiming);
    }

    const int gemm_blocks = (n + 127) / 128;
    const int agg_blocks  = (int)(((long long)n * 32 + 255) / 256);
    const int nb = (n + 1023) / 1024;

    // setup + degree count + dinv (dinv unblocks GEMM1)
    k_setup<<<(n + 255) / 256, 256>>>(W1, W2, n);
    k_count<<<(e + 255) / 256, 256>>>(dst, e);
    k_dinv<<<(n + 255) / 256, 256>>>(n);

    // fork: GEMM1 on side stream; CSR scan/finalize/fill on main stream
    cudaEventRecord(ev1, 0);
    cudaStreamWaitEvent(s2, ev1, 0);
    k_gemm_tc<float><<<gemm_blocks, 256, smem, s2>>>(x, w1h, h, n);
    cudaEventRecord(ev2, s2);

    k_scan_block<<<nb, 1024>>>(n);
    k_finalize<<<(n + 255) / 256, 256>>>(n, nb);
    k_fill<<<(e + 255) / 256, 256>>>(src, dst, e);
    cudaStreamWaitEvent(0, ev2, 0);

    // layer 1 aggregation -> fp16 x2
    k_agg<1><<<agg_blocks, 256>>>(h, b1, x2, n);

    // layer 2
    k_gemm_tc<__half><<<gemm_blocks, 256, smem>>>((const __half*)x2, w2h, h, n);
    k_agg<0><<<agg_blocks, 256>>>(h, b2, d_out, n);
}